// round 2
// baseline (speedup 1.0000x reference)
#include <cuda_runtime.h>
#include <cstdint>

#define E_EDGES   1048576
#define V_SEG     50000
#define V_PAD     50048
#define C_IN      128
#define C_MID     256
#define C_OUT     128

// ---------------- device scratch (no allocations allowed) ----------------
__device__ float g_zvmax[V_PAD * C_MID];        // segment max table (padded)
__device__ float g_zvertex[V_SEG * C_OUT];      // vertex features after W2v
__device__ float g_Wt1[C_IN * C_MID];           // W1^T  (128 x 256) row-major K x N
__device__ float g_Wt2e[C_IN * C_OUT];          // W2e^T (128 x 128)
__device__ float g_Wt2v[C_MID * C_OUT];         // W2v^T (256 x 128)

// ---------------- helpers ----------------
__device__ __forceinline__ void atomicMaxFloat(float* addr, float value) {
    if (value >= 0.0f) {
        atomicMax(reinterpret_cast<int*>(addr), __float_as_int(value));
    } else {
        atomicMin(reinterpret_cast<unsigned int*>(addr), __float_as_uint(value));
    }
}

#define FMA_F32X2(d, a, b) \
    asm("fma.rn.f32x2 %0, %1, %2, %0;" : "+l"(d) : "l"(a), "l"(b))

#define DUP_F32X2(d, s) \
    asm("mov.b64 %0, {%1, %1};" : "=l"(d) : "f"(s))

// ---------------- shared tiled GEMM core ----------------
// C_tile[128,128] += A[arow0:+128, 0:KDIM] * B[0:KDIM, bcol0:+128]
// A row-major with lda == KDIM, B row-major KDIM x NSTRIDE.
// 256 threads, 8x8 per thread, accumulators packed as f32x2 pairs along N.
template <int KDIM, int NSTRIDE, bool FIXNEG>
__device__ __forceinline__ void gemm_core(const float* __restrict__ A,
                                          const float* __restrict__ B,
                                          int arow0, int bcol0,
                                          unsigned long long acc[8][4]) {
    __shared__ float As[16][132];   // transposed A tile, padded
    __shared__ float Bs[16][128];

    const int tid  = threadIdx.x;
    const int tr   = (tid >> 4) << 3;     // 0..120
    const int tc   = (tid & 15) << 3;     // 0..120
    const int lrow = tid >> 1;            // 0..127 (A load row)
    const int lf4  = (tid & 1) << 1;      // 0 or 2 (float4 idx)
    const int brow = tid >> 4;            // 0..15  (B load row)
    const int bc4  = tid & 15;            // 0..15  (B float4 idx)

    for (int k0 = 0; k0 < KDIM; k0 += 16) {
        // --- A tile: 128 rows x 16 k, stored transposed As[k][row]
        const float4* asrc =
            reinterpret_cast<const float4*>(A + (size_t)(arow0 + lrow) * KDIM + k0);
        float4 v0 = __ldg(asrc + lf4);
        float4 v1 = __ldg(asrc + lf4 + 1);
        if (FIXNEG) {
            v0.x = (v0.x < -1e38f) ? 0.0f : v0.x;
            v0.y = (v0.y < -1e38f) ? 0.0f : v0.y;
            v0.z = (v0.z < -1e38f) ? 0.0f : v0.z;
            v0.w = (v0.w < -1e38f) ? 0.0f : v0.w;
            v1.x = (v1.x < -1e38f) ? 0.0f : v1.x;
            v1.y = (v1.y < -1e38f) ? 0.0f : v1.y;
            v1.z = (v1.z < -1e38f) ? 0.0f : v1.z;
            v1.w = (v1.w < -1e38f) ? 0.0f : v1.w;
        }
        {
            int kk = lf4 << 2;
            As[kk + 0][lrow] = v0.x;  As[kk + 1][lrow] = v0.y;
            As[kk + 2][lrow] = v0.z;  As[kk + 3][lrow] = v0.w;
            As[kk + 4][lrow] = v1.x;  As[kk + 5][lrow] = v1.y;
            As[kk + 6][lrow] = v1.z;  As[kk + 7][lrow] = v1.w;
        }
        // --- B tile: 16 k-rows x 128 cols
        const float4* bsrc =
            reinterpret_cast<const float4*>(B + (size_t)(k0 + brow) * NSTRIDE + bcol0);
        float4 w0 = __ldg(bsrc + bc4);
        float4 w1 = __ldg(bsrc + bc4 + 16);
        *reinterpret_cast<float4*>(&Bs[brow][(bc4 << 2)])      = w0;
        *reinterpret_cast<float4*>(&Bs[brow][(bc4 << 2) + 64]) = w1;
        __syncthreads();

#pragma unroll
        for (int k = 0; k < 16; k++) {
            float4 aq0 = *reinterpret_cast<const float4*>(&As[k][tr]);
            float4 aq1 = *reinterpret_cast<const float4*>(&As[k][tr + 4]);
            ulonglong2 bb0 = *reinterpret_cast<const ulonglong2*>(&Bs[k][tc]);
            ulonglong2 bb1 = *reinterpret_cast<const ulonglong2*>(&Bs[k][tc + 4]);
            unsigned long long b2[4] = {bb0.x, bb0.y, bb1.x, bb1.y};
            float af[8] = {aq0.x, aq0.y, aq0.z, aq0.w, aq1.x, aq1.y, aq1.z, aq1.w};
            unsigned long long a2[8];
#pragma unroll
            for (int i = 0; i < 8; i++) DUP_F32X2(a2[i], af[i]);
#pragma unroll
            for (int i = 0; i < 8; i++)
#pragma unroll
                for (int j = 0; j < 4; j++)
                    FMA_F32X2(acc[i][j], a2[i], b2[j]);
        }
        __syncthreads();
    }
}

__device__ __forceinline__ float lo32(unsigned long long v) {
    return __uint_as_float((unsigned)(v & 0xffffffffull));
}
__device__ __forceinline__ float hi32(unsigned long long v) {
    return __uint_as_float((unsigned)(v >> 32));
}

// ---------------- kernels ----------------
__global__ void k_prep(const float* __restrict__ W1,
                       const float* __restrict__ W2e,
                       const float* __restrict__ W2v) {
    int i = blockIdx.x * 256 + threadIdx.x;
    if (i < C_IN * C_MID) {           // 32768: Wt1[k*256+n] = W1[n*128+k]
        int k = i >> 8, n = i & 255;
        g_Wt1[i] = W1[n * C_IN + k];
    }
    if (i < C_IN * C_OUT) {           // 16384: Wt2e[k*128+n] = W2e[n*128+k]
        int k = i >> 7, n = i & 127;
        g_Wt2e[i] = W2e[n * C_IN + k];
    }
    if (i < C_MID * C_OUT) {          // 32768: Wt2v[k*128+n] = W2v[n*256+k]
        int k = i >> 7, n = i & 127;
        g_Wt2v[i] = W2v[n * C_MID + k];
    }
}

__global__ void k_init_zvmax() {
    int i = blockIdx.x * blockDim.x + threadIdx.x;
    const float NEG_INF = __int_as_float(0xFF800000);
    float4 v = make_float4(NEG_INF, NEG_INF, NEG_INF, NEG_INF);
    if (i < (V_PAD * C_MID) / 4)
        reinterpret_cast<float4*>(g_zvmax)[i] = v;
}

// GEMM1: z = x @ W1^T + b1, then atomic segment-max into g_zvmax
__global__ void __launch_bounds__(256, 2)
k_gemm1(const float* __restrict__ x,
        const float* __restrict__ b1,
        const int* __restrict__ vid) {
    unsigned long long acc[8][4] = {};
    int arow0 = blockIdx.x * 128;
    int bcol0 = blockIdx.y * 128;
    gemm_core<C_IN, C_MID, false>(x, g_Wt1, arow0, bcol0, acc);

    const int tid = threadIdx.x;
    const int tr = (tid >> 4) << 3;
    const int tc = (tid & 15) << 3;
    float4 bi0 = *reinterpret_cast<const float4*>(&b1[bcol0 + tc]);
    float4 bi1 = *reinterpret_cast<const float4*>(&b1[bcol0 + tc + 4]);
    float bb[8] = {bi0.x, bi0.y, bi0.z, bi0.w, bi1.x, bi1.y, bi1.z, bi1.w};

#pragma unroll
    for (int i = 0; i < 8; i++) {
        int erow = arow0 + tr + i;
        int v = __ldg(&vid[erow]);
        float* dst = g_zvmax + (size_t)v * C_MID + bcol0 + tc;
#pragma unroll
        for (int j = 0; j < 4; j++) {
            atomicMaxFloat(dst + 2 * j,     lo32(acc[i][j]) + bb[2 * j]);
            atomicMaxFloat(dst + 2 * j + 1, hi32(acc[i][j]) + bb[2 * j + 1]);
        }
    }
}

// GEMM2: z_vertex = fix(z_vmax) @ W2v^T
__global__ void __launch_bounds__(256, 2)
k_gemm2() {
    unsigned long long acc[8][4] = {};
    int arow0 = blockIdx.x * 128;
    gemm_core<C_MID, C_OUT, true>(g_zvmax, g_Wt2v, arow0, 0, acc);

    const int tid = threadIdx.x;
    const int tr = (tid >> 4) << 3;
    const int tc = (tid & 15) << 3;
#pragma unroll
    for (int i = 0; i < 8; i++) {
        int vrow = arow0 + tr + i;
        if (vrow < V_SEG) {
            float4 o0 = make_float4(lo32(acc[i][0]), hi32(acc[i][0]),
                                    lo32(acc[i][1]), hi32(acc[i][1]));
            float4 o1 = make_float4(lo32(acc[i][2]), hi32(acc[i][2]),
                                    lo32(acc[i][3]), hi32(acc[i][3]));
            *reinterpret_cast<float4*>(&g_zvertex[(size_t)vrow * C_OUT + tc])     = o0;
            *reinterpret_cast<float4*>(&g_zvertex[(size_t)vrow * C_OUT + tc + 4]) = o1;
        }
    }
}

// GEMM3: out = x @ W2e^T + z_vertex[vid]
__global__ void __launch_bounds__(256, 2)
k_gemm3(const float* __restrict__ x,
        const int* __restrict__ vid,
        float* __restrict__ out) {
    unsigned long long acc[8][4] = {};
    int arow0 = blockIdx.x * 128;
    gemm_core<C_IN, C_OUT, false>(x, g_Wt2e, arow0, 0, acc);

    const int tid = threadIdx.x;
    const int tr = (tid >> 4) << 3;
    const int tc = (tid & 15) << 3;
#pragma unroll
    for (int i = 0; i < 8; i++) {
        int erow = arow0 + tr + i;
        int v = __ldg(&vid[erow]);
        const float4* zp =
            reinterpret_cast<const float4*>(g_zvertex + (size_t)v * C_OUT + tc);
        float4 z0 = __ldg(zp);
        float4 z1 = __ldg(zp + 1);
        float4 o0 = make_float4(lo32(acc[i][0]) + z0.x, hi32(acc[i][0]) + z0.y,
                                lo32(acc[i][1]) + z0.z, hi32(acc[i][1]) + z0.w);
        float4 o1 = make_float4(lo32(acc[i][2]) + z1.x, hi32(acc[i][2]) + z1.y,
                                lo32(acc[i][3]) + z1.z, hi32(acc[i][3]) + z1.w);
        *reinterpret_cast<float4*>(&out[(size_t)erow * C_OUT + tc])     = o0;
        *reinterpret_cast<float4*>(&out[(size_t)erow * C_OUT + tc + 4]) = o1;
    }
}

// ---------------- launch ----------------
extern "C" void kernel_launch(void* const* d_in, const int* in_sizes, int n_in,
                              void* d_out, int out_size) {
    const float* x   = (const float*)d_in[0];
    const int*   vid = (const int*)d_in[1];
    const float* W1  = (const float*)d_in[2];
    const float* b1  = (const float*)d_in[3];
    const float* W2e = (const float*)d_in[4];
    const float* W2v = (const float*)d_in[5];
    float* out = (float*)d_out;

    k_prep<<<128, 256>>>(W1, W2e, W2v);
    k_init_zvmax<<<(V_PAD * C_MID / 4 + 255) / 256, 256>>>();
    k_gemm1<<<dim3(E_EDGES / 128, C_MID / 128), 256>>>(x, b1, vid);
    k_gemm2<<<(V_PAD + 127) / 128, 256>>>();
    k_gemm3<<<E_EDGES / 128, 256>>>(x, vid, out);
}

// round 4
// speedup vs baseline: 3.1045x; 3.1045x over previous
#include <cuda_runtime.h>
#include <cuda_bf16.h>
#include <cstdint>

#define E_EDGES   1048576
#define V_SEG     50000
#define V_PAD     50048
#define C_IN      128
#define C_MID     256
#define C_OUT     128
#define KTOT      384      // 3 x 128 split-K (hi*whi + lo*whi + hi*wlo)
#define NCHUNK    6        // KTOT / 64

// ---------------- device scratch ----------------
__device__ __align__(16) __nv_bfloat16 g_xhi[(size_t)E_EDGES * C_IN];
__device__ __align__(16) __nv_bfloat16 g_xlo[(size_t)E_EDGES * C_IN];
__device__ __align__(16) __nv_bfloat16 g_B1[C_MID * KTOT];   // [256][384] = [Whi|Whi|Wlo]
__device__ __align__(16) __nv_bfloat16 g_B3[C_OUT * KTOT];   // [128][384]
__device__ float g_Wt2v[C_MID * C_OUT];                      // W2v^T (256 x 128)
__device__ float g_zvmax[V_PAD * C_MID];
__device__ float g_zvertex[V_SEG * C_OUT];

// ---------------- helpers ----------------
__device__ __forceinline__ uint32_t smem_to_u32(const void* p) {
    uint32_t a;
    asm("{ .reg .u64 t; cvta.to.shared.u64 t, %1; cvt.u32.u64 %0, t; }" : "=r"(a) : "l"(p));
    return a;
}
#define SWZ(o) ((o) ^ (((o) >> 3) & 0x70))

#define CP_ASYNC16(dst, src) \
    asm volatile("cp.async.cg.shared.global [%0], [%1], 16;" :: "r"(dst), "l"(src))
#define CP_COMMIT() asm volatile("cp.async.commit_group;" ::: "memory")
#define CP_WAIT1()  asm volatile("cp.async.wait_group 1;" ::: "memory")
#define CP_WAIT0()  asm volatile("cp.async.wait_group 0;" ::: "memory")

#define LDSM_X4(r0, r1, r2, r3, addr) \
    asm volatile("ldmatrix.sync.aligned.m8n8.x4.shared.b16 {%0,%1,%2,%3}, [%4];" \
                 : "=r"(r0), "=r"(r1), "=r"(r2), "=r"(r3) : "r"(addr))

#define MMA16816(d, a, b) \
    asm volatile("mma.sync.aligned.m16n8k16.row.col.f32.bf16.bf16.f32 " \
                 "{%0,%1,%2,%3}, {%4,%5,%6,%7}, {%8,%9}, {%0,%1,%2,%3};" \
                 : "+f"((d)[0]), "+f"((d)[1]), "+f"((d)[2]), "+f"((d)[3]) \
                 : "r"((a)[0]), "r"((a)[1]), "r"((a)[2]), "r"((a)[3]), \
                   "r"((b)[0]), "r"((b)[1]))

__device__ __forceinline__ void atomicMaxFloat(float* addr, float value) {
    if (value >= 0.0f) atomicMax(reinterpret_cast<int*>(addr), __float_as_int(value));
    else               atomicMin(reinterpret_cast<unsigned int*>(addr), __float_as_uint(value));
}

// ---------------- mma mainloop pieces ----------------
// A stage: 128 rows x 64 k bf16 (row stride in gmem = 256 B); B stage: 128 n-rows x 64 k
// (row stride in gmem = 768 B). Both stored swizzled SW128, 128 B per smem row.
__device__ __forceinline__ void load_stage(uint32_t sA, uint32_t sB,
                                           const char* abase, const char* bbase, int tid) {
#pragma unroll
    for (int i = 0; i < 4; i++) {
        int idx = i * 256 + tid;
        int row = idx >> 3, col = (idx & 7) << 4;
        CP_ASYNC16(sA + SWZ(row * 128 + col), abase + (size_t)row * 256 + col);
    }
#pragma unroll
    for (int i = 0; i < 4; i++) {
        int idx = i * 256 + tid;
        int row = idx >> 3, col = (idx & 7) << 4;
        CP_ASYNC16(sB + SWZ(row * 128 + col), bbase + (size_t)row * 768 + col);
    }
    CP_COMMIT();
}

__device__ __forceinline__ void compute_stage(uint32_t sA, uint32_t sB,
                                              float acc[2][8][4],
                                              int lane, int warp_m, int warp_n) {
    const int g = lane >> 3, lr = lane & 7;
#pragma unroll
    for (int ks = 0; ks < 4; ks++) {
        uint32_t a[2][4];
#pragma unroll
        for (int mi = 0; mi < 2; mi++) {
            int row = warp_m * 32 + mi * 16 + lr + ((g & 1) << 3);
            int kb  = ks * 32 + ((g >> 1) << 4);
            LDSM_X4(a[mi][0], a[mi][1], a[mi][2], a[mi][3], sA + SWZ(row * 128 + kb));
        }
        uint32_t b[8][2];
#pragma unroll
        for (int nj2 = 0; nj2 < 4; nj2++) {
            int nrow = warp_n * 64 + nj2 * 16 + lr + ((g >> 1) << 3);
            int kb   = ks * 32 + ((g & 1) << 4);
            uint32_t r0, r1, r2, r3;
            LDSM_X4(r0, r1, r2, r3, sB + SWZ(nrow * 128 + kb));
            b[nj2 * 2][0] = r0;     b[nj2 * 2][1] = r1;
            b[nj2 * 2 + 1][0] = r2; b[nj2 * 2 + 1][1] = r3;
        }
#pragma unroll
        for (int mi = 0; mi < 2; mi++)
#pragma unroll
            for (int nj = 0; nj < 8; nj++)
                MMA16816(acc[mi][nj], a[mi], b[nj]);
    }
}

__device__ __forceinline__ void mma_mainloop(const __nv_bfloat16* __restrict__ Bmat,
                                             int arow0, int bcol0,
                                             uint32_t sbase, float acc[2][8][4],
                                             int tid, int lane, int warp_m, int warp_n) {
    uint32_t sA[2] = {sbase, sbase + 16384};
    uint32_t sB[2] = {sbase + 32768, sbase + 49152};
    const char* xh = (const char*)g_xhi + (size_t)arow0 * 256;
    const char* xl = (const char*)g_xlo + (size_t)arow0 * 256;
    const char* bb = (const char*)Bmat + (size_t)bcol0 * (KTOT * 2);

    // chunk c: A = {0:hi k0, 1:hi k1, 2:lo k0, 3:lo k1, 4:hi k0, 5:hi k1}
    const char* abase[NCHUNK] = {xh, xh + 128, xl, xl + 128, xh, xh + 128};

    load_stage(sA[0], sB[0], abase[0], bb, tid);
#pragma unroll
    for (int c = 0; c < NCHUNK; c++) {
        if (c < NCHUNK - 1) {
            load_stage(sA[(c + 1) & 1], sB[(c + 1) & 1], abase[c + 1], bb + (c + 1) * 128, tid);
            CP_WAIT1();
        } else {
            CP_WAIT0();
        }
        __syncthreads();
        compute_stage(sA[c & 1], sB[c & 1], acc, lane, warp_m, warp_n);
        __syncthreads();
    }
}

// ---------------- prep kernels ----------------
__global__ void k_prep_w(const float* __restrict__ W1,
                         const float* __restrict__ W2e,
                         const float* __restrict__ W2v) {
    int i = blockIdx.x * 256 + threadIdx.x;
    if (i < C_MID * C_IN) {     // W1 (256,128) -> g_B1 [256][384] = [hi | hi | lo]
        int n = i >> 7, k = i & 127;
        float w = W1[i];
        __nv_bfloat16 hi = __float2bfloat16(w);
        __nv_bfloat16 lo = __float2bfloat16(w - __bfloat162float(hi));
        g_B1[n * KTOT + k] = hi;
        g_B1[n * KTOT + 128 + k] = hi;
        g_B1[n * KTOT + 256 + k] = lo;
    }
    if (i < C_OUT * C_IN) {     // W2e (128,128) -> g_B3
        int n = i >> 7, k = i & 127;
        float w = W2e[i];
        __nv_bfloat16 hi = __float2bfloat16(w);
        __nv_bfloat16 lo = __float2bfloat16(w - __bfloat162float(hi));
        g_B3[n * KTOT + k] = hi;
        g_B3[n * KTOT + 128 + k] = hi;
        g_B3[n * KTOT + 256 + k] = lo;
    }
    if (i < C_MID * C_OUT) {    // W2v (128,256) -> g_Wt2v [k*128+n]
        int k = i >> 7, n = i & 127;
        g_Wt2v[i] = W2v[n * C_MID + k];
    }
}

__global__ void k_split_x(const float* __restrict__ x) {
    size_t i = (size_t)blockIdx.x * 256 + threadIdx.x;   // unit = 4 floats
    float4 v = __ldg(reinterpret_cast<const float4*>(x) + i);
    ushort4 h, l;
    __nv_bfloat16 hb, lb;
    hb = __float2bfloat16(v.x); lb = __float2bfloat16(v.x - __bfloat162float(hb));
    h.x = *(unsigned short*)&hb; l.x = *(unsigned short*)&lb;
    hb = __float2bfloat16(v.y); lb = __float2bfloat16(v.y - __bfloat162float(hb));
    h.y = *(unsigned short*)&hb; l.y = *(unsigned short*)&lb;
    hb = __float2bfloat16(v.z); lb = __float2bfloat16(v.z - __bfloat162float(hb));
    h.z = *(unsigned short*)&hb; l.z = *(unsigned short*)&lb;
    hb = __float2bfloat16(v.w); lb = __float2bfloat16(v.w - __bfloat162float(hb));
    h.w = *(unsigned short*)&hb; l.w = *(unsigned short*)&lb;
    reinterpret_cast<ushort4*>(g_xhi)[i] = h;
    reinterpret_cast<ushort4*>(g_xlo)[i] = l;
}

__global__ void k_init_zvmax() {
    int i = blockIdx.x * blockDim.x + threadIdx.x;
    const float NEG_INF = __int_as_float(0xFF800000);
    if (i < (V_PAD * C_MID) / 4)
        reinterpret_cast<float4*>(g_zvmax)[i] = make_float4(NEG_INF, NEG_INF, NEG_INF, NEG_INF);
}

// ---------------- GEMM1: z = x@W1^T (no bias), atomic segment-max ----------------
// grid (2, 8192): x = N-half (L2 pairing), y = row tile
__global__ void __launch_bounds__(256, 2)
k_mma1(const int* __restrict__ vid) {
    extern __shared__ char smem[];
    uint32_t sbase = smem_to_u32(smem);
    const int tid = threadIdx.x, wid = tid >> 5, lane = tid & 31;
    const int warp_m = wid & 3, warp_n = wid >> 2;
    const int arow0 = blockIdx.y * 128, bcol0 = blockIdx.x * 128;

    float acc[2][8][4] = {};
    mma_mainloop(g_B1, arow0, bcol0, sbase, acc, tid, lane, warp_m, warp_n);

    const int lr4 = lane >> 2, lc2 = (lane & 3) * 2;
#pragma unroll
    for (int mi = 0; mi < 2; mi++) {
        int r0 = arow0 + warp_m * 32 + mi * 16 + lr4;
        int v0 = __ldg(&vid[r0]);
        int v1 = __ldg(&vid[r0 + 8]);
        float* p0 = g_zvmax + (size_t)v0 * C_MID + bcol0 + warp_n * 64 + lc2;
        float* p1 = g_zvmax + (size_t)v1 * C_MID + bcol0 + warp_n * 64 + lc2;
#pragma unroll
        for (int nj = 0; nj < 8; nj++) {
            atomicMaxFloat(p0 + nj * 8,     acc[mi][nj][0]);
            atomicMaxFloat(p0 + nj * 8 + 1, acc[mi][nj][1]);
            atomicMaxFloat(p1 + nj * 8,     acc[mi][nj][2]);
            atomicMaxFloat(p1 + nj * 8 + 1, acc[mi][nj][3]);
        }
    }
}

// ---------------- GEMM3: out = x@W2e^T + z_vertex[vid] ----------------
__global__ void __launch_bounds__(256, 2)
k_mma3(const int* __restrict__ vid, float* __restrict__ out) {
    extern __shared__ char smem[];
    uint32_t sbase = smem_to_u32(smem);
    const int tid = threadIdx.x, wid = tid >> 5, lane = tid & 31;
    const int warp_m = wid & 3, warp_n = wid >> 2;
    const int arow0 = blockIdx.y * 128;

    float acc[2][8][4] = {};
    mma_mainloop(g_B3, arow0, 0, sbase, acc, tid, lane, warp_m, warp_n);

    const int lr4 = lane >> 2, lc2 = (lane & 3) * 2;
#pragma unroll
    for (int mi = 0; mi < 2; mi++) {
        int r0 = arow0 + warp_m * 32 + mi * 16 + lr4;
        int r1 = r0 + 8;
        int v0 = __ldg(&vid[r0]);
        int v1 = __ldg(&vid[r1]);
        const float* z0 = g_zvertex + (size_t)v0 * C_OUT + warp_n * 64 + lc2;
        const float* z1 = g_zvertex + (size_t)v1 * C_OUT + warp_n * 64 + lc2;
        float* o0 = out + (size_t)r0 * C_OUT + warp_n * 64 + lc2;
        float* o1 = out + (size_t)r1 * C_OUT + warp_n * 64 + lc2;
#pragma unroll
        for (int nj = 0; nj < 8; nj++) {
            float2 za = __ldg(reinterpret_cast<const float2*>(z0 + nj * 8));
            float2 zb = __ldg(reinterpret_cast<const float2*>(z1 + nj * 8));
            *reinterpret_cast<float2*>(o0 + nj * 8) =
                make_float2(acc[mi][nj][0] + za.x, acc[mi][nj][1] + za.y);
            *reinterpret_cast<float2*>(o1 + nj * 8) =
                make_float2(acc[mi][nj][2] + zb.x, acc[mi][nj][3] + zb.y);
        }
    }
}

// ---------------- GEMM2 (FFMA, small): z_vertex = fix(z_vmax + b1) @ W2v^T ----------------
#define FMA_F32X2(d, a, b) asm("fma.rn.f32x2 %0, %1, %2, %0;" : "+l"(d) : "l"(a), "l"(b))
#define DUP_F32X2(d, s)    asm("mov.b64 %0, {%1, %1};" : "=l"(d) : "f"(s))
__device__ __forceinline__ float lo32(unsigned long long v) {
    return __uint_as_float((unsigned)(v & 0xffffffffull));
}
__device__ __forceinline__ float hi32(unsigned long long v) {
    return __uint_as_float((unsigned)(v >> 32));
}

__global__ void __launch_bounds__(256, 2)
k_gemm2(const float* __restrict__ b1) {
    __shared__ float As[16][132];
    __shared__ float Bs[16][128];
    unsigned long long acc[8][4] = {};
    const int arow0 = blockIdx.x * 128;
    const int tid = threadIdx.x;
    const int tr = (tid >> 4) << 3, tc = (tid & 15) << 3;
    const int lrow = tid >> 1, lf4 = (tid & 1) << 1;
    const int brow = tid >> 4, bc4 = tid & 15;

    for (int k0 = 0; k0 < C_MID; k0 += 16) {
        const float4* asrc = reinterpret_cast<const float4*>(
            g_zvmax + (size_t)(arow0 + lrow) * C_MID + k0);
        float4 v0 = __ldg(asrc + lf4);
        float4 v1 = __ldg(asrc + lf4 + 1);
        float4 bb0 = *reinterpret_cast<const float4*>(&b1[k0 + lf4 * 4]);
        float4 bb1 = *reinterpret_cast<const float4*>(&b1[k0 + lf4 * 4 + 4]);
        v0.x = (v0.x < -1e38f) ? 0.0f : v0.x + bb0.x;
        v0.y = (v0.y < -1e38f) ? 0.0f : v0.y + bb0.y;
        v0.z = (v0.z < -1e38f) ? 0.0f : v0.z + bb0.z;
        v0.w = (v0.w < -1e38f) ? 0.0f : v0.w + bb0.w;
        v1.x = (v1.x < -1e38f) ? 0.0f : v1.x + bb1.x;
        v1.y = (v1.y < -1e38f) ? 0.0f : v1.y + bb1.y;
        v1.z = (v1.z < -1e38f) ? 0.0f : v1.z + bb1.z;
        v1.w = (v1.w < -1e38f) ? 0.0f : v1.w + bb1.w;
        {
            int kk = lf4 << 2;
            As[kk + 0][lrow] = v0.x;  As[kk + 1][lrow] = v0.y;
            As[kk + 2][lrow] = v0.z;  As[kk + 3][lrow] = v0.w;
            As[kk + 4][lrow] = v1.x;  As[kk + 5][lrow] = v1.y;
            As[kk + 6][lrow] = v1.z;  As[kk + 7][lrow] = v1.w;
        }
        const float4* bsrc = reinterpret_cast<const float4*>(
            g_Wt2v + (size_t)(k0 + brow) * C_OUT);
        float4 w0 = __ldg(bsrc + bc4);
        float4 w1 = __ldg(bsrc + bc4 + 16);
        *reinterpret_cast<float4*>(&Bs[brow][(bc4 << 2)])      = w0;
        *reinterpret_cast<float4*>(&Bs[brow][(bc4 << 2) + 64]) = w1;
        __syncthreads();
#pragma unroll
        for (int k = 0; k < 16; k++) {
            float4 aq0 = *reinterpret_cast<const float4*>(&As[k][tr]);
            float4 aq1 = *reinterpret_cast<const float4*>(&As[k][tr + 4]);
            ulonglong2 b0 = *reinterpret_cast<const ulonglong2*>(&Bs[k][tc]);
            ulonglong2 b1v = *reinterpret_cast<const ulonglong2*>(&Bs[k][tc + 4]);
            unsigned long long b2[4] = {b0.x, b0.y, b1v.x, b1v.y};
            float af[8] = {aq0.x, aq0.y, aq0.z, aq0.w, aq1.x, aq1.y, aq1.z, aq1.w};
            unsigned long long a2[8];
#pragma unroll
            for (int i = 0; i < 8; i++) DUP_F32X2(a2[i], af[i]);
#pragma unroll
            for (int i = 0; i < 8; i++)
#pragma unroll
                for (int j = 0; j < 4; j++) FMA_F32X2(acc[i][j], a2[i], b2[j]);
        }
        __syncthreads();
    }
#pragma unroll
    for (int i = 0; i < 8; i++) {
        int vrow = arow0 + tr + i;
        if (vrow < V_SEG) {
            float4 o0 = make_float4(lo32(acc[i][0]), hi32(acc[i][0]),
                                    lo32(acc[i][1]), hi32(acc[i][1]));
            float4 o1 = make_float4(lo32(acc[i][2]), hi32(acc[i][2]),
                                    lo32(acc[i][3]), hi32(acc[i][3]));
            *reinterpret_cast<float4*>(&g_zvertex[(size_t)vrow * C_OUT + tc])     = o0;
            *reinterpret_cast<float4*>(&g_zvertex[(size_t)vrow * C_OUT + tc + 4]) = o1;
        }
    }
}

// ---------------- launch ----------------
static constexpr int SMEM_MMA = 65536;   // 2 x (16KB A + 16KB B)

extern "C" void kernel_launch(void* const* d_in, const int* in_sizes, int n_in,
                              void* d_out, int out_size) {
    const float* x   = (const float*)d_in[0];
    const int*   vid = (const int*)d_in[1];
    const float* W1  = (const float*)d_in[2];
    const float* b1  = (const float*)d_in[3];
    const float* W2e = (const float*)d_in[4];
    const float* W2v = (const float*)d_in[5];
    float* out = (float*)d_out;

    cudaFuncSetAttribute(k_mma1, cudaFuncAttributeMaxDynamicSharedMemorySize, SMEM_MMA);
    cudaFuncSetAttribute(k_mma3, cudaFuncAttributeMaxDynamicSharedMemorySize, SMEM_MMA);

    k_prep_w<<<128, 256>>>(W1, W2e, W2v);
    k_split_x<<<(E_EDGES * C_IN / 4) / 256, 256>>>(x);
    k_init_zvmax<<<(V_PAD * C_MID / 4 + 255) / 256, 256>>>();
    k_mma1<<<dim3(2, E_EDGES / 128), 256, SMEM_MMA>>>(vid);
    k_gemm2<<<V_PAD / 128, 256>>>(b1);
    k_mma3<<<dim3(1, E_EDGES / 128), 256, SMEM_MMA>>>(vid, out);
}

// round 5
// speedup vs baseline: 3.5320x; 1.1377x over previous
#include <cuda_runtime.h>
#include <cuda_bf16.h>
#include <cstdint>

#define E_EDGES   1048576
#define V_SEG     50000
#define V_PAD     50048
#define C_IN      128
#define C_MID     256
#define C_OUT     128
#define KTOT      384      // 3 x 128 split-K (hi*whi + lo*whi + hi*wlo)
#define NCHUNK    6        // KTOT / 64

// ---------------- device scratch ----------------
__device__ __align__(16) __nv_bfloat16 g_xhi[(size_t)E_EDGES * C_IN];   // sorted order
__device__ __align__(16) __nv_bfloat16 g_xlo[(size_t)E_EDGES * C_IN];   // sorted order
__device__ __align__(16) __nv_bfloat16 g_B1[C_MID * KTOT];   // [256][384] = [Whi|Whi|Wlo]
__device__ __align__(16) __nv_bfloat16 g_B3[C_OUT * KTOT];   // [128][384]
__device__ float g_Wt2v[C_MID * C_OUT];                      // W2v^T (256 x 128)
__device__ float g_zvmax[V_PAD * C_MID];
__device__ float g_zvertex[V_SEG * C_OUT];
// counting sort
__device__ unsigned g_count[V_PAD];
__device__ unsigned g_offset[V_PAD];
__device__ int g_order[E_EDGES];   // sorted pos -> original edge
__device__ int g_svid[E_EDGES];   // vid in sorted order (non-decreasing)

// ---------------- helpers ----------------
__device__ __forceinline__ uint32_t smem_to_u32(const void* p) {
    uint32_t a;
    asm("{ .reg .u64 t; cvta.to.shared.u64 t, %1; cvt.u32.u64 %0, t; }" : "=r"(a) : "l"(p));
    return a;
}
#define SWZ(o) ((o) ^ (((o) >> 3) & 0x70))

#define CP_ASYNC16(dst, src) \
    asm volatile("cp.async.cg.shared.global [%0], [%1], 16;" :: "r"(dst), "l"(src))
#define CP_COMMIT() asm volatile("cp.async.commit_group;" ::: "memory")
#define CP_WAIT1()  asm volatile("cp.async.wait_group 1;" ::: "memory")
#define CP_WAIT0()  asm volatile("cp.async.wait_group 0;" ::: "memory")

#define LDSM_X4(r0, r1, r2, r3, addr) \
    asm volatile("ldmatrix.sync.aligned.m8n8.x4.shared.b16 {%0,%1,%2,%3}, [%4];" \
                 : "=r"(r0), "=r"(r1), "=r"(r2), "=r"(r3) : "r"(addr))

#define MMA16816(d, a, b) \
    asm volatile("mma.sync.aligned.m16n8k16.row.col.f32.bf16.bf16.f32 " \
                 "{%0,%1,%2,%3}, {%4,%5,%6,%7}, {%8,%9}, {%0,%1,%2,%3};" \
                 : "+f"((d)[0]), "+f"((d)[1]), "+f"((d)[2]), "+f"((d)[3]) \
                 : "r"((a)[0]), "r"((a)[1]), "r"((a)[2]), "r"((a)[3]), \
                   "r"((b)[0]), "r"((b)[1]))

__device__ __forceinline__ void atomicMaxFloat(float* addr, float value) {
    if (value >= 0.0f) atomicMax(reinterpret_cast<int*>(addr), __float_as_int(value));
    else               atomicMin(reinterpret_cast<unsigned int*>(addr), __float_as_uint(value));
}

// ---------------- mma mainloop (identical to R4 passing version) ----------------
__device__ __forceinline__ void load_stage(uint32_t sA, uint32_t sB,
                                           const char* abase, const char* bbase, int tid) {
#pragma unroll
    for (int i = 0; i < 4; i++) {
        int idx = i * 256 + tid;
        int row = idx >> 3, col = (idx & 7) << 4;
        CP_ASYNC16(sA + SWZ(row * 128 + col), abase + (size_t)row * 256 + col);
    }
#pragma unroll
    for (int i = 0; i < 4; i++) {
        int idx = i * 256 + tid;
        int row = idx >> 3, col = (idx & 7) << 4;
        CP_ASYNC16(sB + SWZ(row * 128 + col), bbase + (size_t)row * 768 + col);
    }
    CP_COMMIT();
}

__device__ __forceinline__ void compute_stage(uint32_t sA, uint32_t sB,
                                              float acc[2][8][4],
                                              int lane, int warp_m, int warp_n) {
    const int g = lane >> 3, lr = lane & 7;
#pragma unroll
    for (int ks = 0; ks < 4; ks++) {
        uint32_t a[2][4];
#pragma unroll
        for (int mi = 0; mi < 2; mi++) {
            int row = warp_m * 32 + mi * 16 + lr + ((g & 1) << 3);
            int kb  = ks * 32 + ((g >> 1) << 4);
            LDSM_X4(a[mi][0], a[mi][1], a[mi][2], a[mi][3], sA + SWZ(row * 128 + kb));
        }
        uint32_t b[8][2];
#pragma unroll
        for (int nj2 = 0; nj2 < 4; nj2++) {
            int nrow = warp_n * 64 + nj2 * 16 + lr + ((g >> 1) << 3);
            int kb   = ks * 32 + ((g & 1) << 4);
            uint32_t r0, r1, r2, r3;
            LDSM_X4(r0, r1, r2, r3, sB + SWZ(nrow * 128 + kb));
            b[nj2 * 2][0] = r0;     b[nj2 * 2][1] = r1;
            b[nj2 * 2 + 1][0] = r2; b[nj2 * 2 + 1][1] = r3;
        }
#pragma unroll
        for (int mi = 0; mi < 2; mi++)
#pragma unroll
            for (int nj = 0; nj < 8; nj++)
                MMA16816(acc[mi][nj], a[mi], b[nj]);
    }
}

__device__ __forceinline__ void mma_mainloop(const __nv_bfloat16* __restrict__ Bmat,
                                             int arow0, int bcol0,
                                             uint32_t sbase, float acc[2][8][4],
                                             int tid, int lane, int warp_m, int warp_n) {
    uint32_t sA[2] = {sbase, sbase + 16384};
    uint32_t sB[2] = {sbase + 32768, sbase + 49152};
    const char* xh = (const char*)g_xhi + (size_t)arow0 * 256;
    const char* xl = (const char*)g_xlo + (size_t)arow0 * 256;
    const char* bb = (const char*)Bmat + (size_t)bcol0 * (KTOT * 2);

    const char* abase[NCHUNK] = {xh, xh + 128, xl, xl + 128, xh, xh + 128};

    load_stage(sA[0], sB[0], abase[0], bb, tid);
#pragma unroll
    for (int c = 0; c < NCHUNK; c++) {
        if (c < NCHUNK - 1) {
            load_stage(sA[(c + 1) & 1], sB[(c + 1) & 1], abase[c + 1], bb + (c + 1) * 128, tid);
            CP_WAIT1();
        } else {
            CP_WAIT0();
        }
        __syncthreads();
        compute_stage(sA[c & 1], sB[c & 1], acc, lane, warp_m, warp_n);
        __syncthreads();
    }
}

// ---------------- counting sort by vertex_id ----------------
__global__ void k_zero_count() {
    int i = blockIdx.x * 256 + threadIdx.x;
    if (i < V_PAD) g_count[i] = 0;
}

__global__ void k_hist(const int* __restrict__ vid) {
    int e = blockIdx.x * 256 + threadIdx.x;
    atomicAdd(&g_count[__ldg(&vid[e])], 1u);
}

__global__ void k_scan() {   // single block, 1024 threads
    __shared__ unsigned s_part[1024];
    const int t = threadIdx.x;
    const int PER = (V_PAD + 1023) / 1024;   // 49
    int base = t * PER;
    unsigned sum = 0;
    for (int i = 0; i < PER; i++) {
        int b = base + i;
        if (b < V_PAD) sum += g_count[b];
    }
    s_part[t] = sum;
    __syncthreads();
    for (int off = 1; off < 1024; off <<= 1) {
        unsigned v = (t >= off) ? s_part[t - off] : 0u;
        __syncthreads();
        s_part[t] += v;
        __syncthreads();
    }
    unsigned run = s_part[t] - sum;   // exclusive prefix
    for (int i = 0; i < PER; i++) {
        int b = base + i;
        if (b < V_PAD) {
            g_offset[b] = run;
            run += g_count[b];
        }
    }
}

__global__ void k_scatter(const int* __restrict__ vid) {
    int e = blockIdx.x * 256 + threadIdx.x;
    int v = __ldg(&vid[e]);
    unsigned p = atomicAdd(&g_offset[v], 1u);
    g_order[p] = e;
    g_svid[p] = v;
}

// ---------------- prep kernels ----------------
__global__ void k_prep_w(const float* __restrict__ W1,
                         const float* __restrict__ W2e,
                         const float* __restrict__ W2v) {
    int i = blockIdx.x * 256 + threadIdx.x;
    if (i < C_MID * C_IN) {
        int n = i >> 7, k = i & 127;
        float w = W1[i];
        __nv_bfloat16 hi = __float2bfloat16(w);
        __nv_bfloat16 lo = __float2bfloat16(w - __bfloat162float(hi));
        g_B1[n * KTOT + k] = hi;
        g_B1[n * KTOT + 128 + k] = hi;
        g_B1[n * KTOT + 256 + k] = lo;
    }
    if (i < C_OUT * C_IN) {
        int n = i >> 7, k = i & 127;
        float w = W2e[i];
        __nv_bfloat16 hi = __float2bfloat16(w);
        __nv_bfloat16 lo = __float2bfloat16(w - __bfloat162float(hi));
        g_B3[n * KTOT + k] = hi;
        g_B3[n * KTOT + 128 + k] = hi;
        g_B3[n * KTOT + 256 + k] = lo;
    }
    if (i < C_MID * C_OUT) {
        int k = i >> 7, n = i & 127;
        g_Wt2v[i] = W2v[n * C_MID + k];
    }
}

// gather-split: sorted row p <- original edge order[p]
__global__ void k_split_x(const float* __restrict__ x) {
    size_t i = (size_t)blockIdx.x * 256 + threadIdx.x;   // unit = 4 floats
    int prow = (int)(i >> 5);            // 32 units per 128-float row
    int q = (int)(i & 31);
    int e = __ldg(&g_order[prow]);
    float4 v = __ldg(reinterpret_cast<const float4*>(x + (size_t)e * C_IN) + q);
    ushort4 h, l;
    __nv_bfloat16 hb, lb;
    hb = __float2bfloat16(v.x); lb = __float2bfloat16(v.x - __bfloat162float(hb));
    h.x = *(unsigned short*)&hb; l.x = *(unsigned short*)&lb;
    hb = __float2bfloat16(v.y); lb = __float2bfloat16(v.y - __bfloat162float(hb));
    h.y = *(unsigned short*)&hb; l.y = *(unsigned short*)&lb;
    hb = __float2bfloat16(v.z); lb = __float2bfloat16(v.z - __bfloat162float(hb));
    h.z = *(unsigned short*)&hb; l.z = *(unsigned short*)&lb;
    hb = __float2bfloat16(v.w); lb = __float2bfloat16(v.w - __bfloat162float(hb));
    h.w = *(unsigned short*)&hb; l.w = *(unsigned short*)&lb;
    reinterpret_cast<ushort4*>(g_xhi)[i] = h;
    reinterpret_cast<ushort4*>(g_xlo)[i] = l;
}

__global__ void k_init_zvmax() {
    int i = blockIdx.x * blockDim.x + threadIdx.x;
    const float NEG_INF = __int_as_float(0xFF800000);
    if (i < (V_PAD * C_MID) / 4)
        reinterpret_cast<float4*>(g_zvmax)[i] = make_float4(NEG_INF, NEG_INF, NEG_INF, NEG_INF);
}

// ---------------- GEMM1: z = xs@W1^T, in-tile run-max over sorted vids, few atomics ----------------
__global__ void __launch_bounds__(256, 2)
k_mma1() {
    extern __shared__ char smem[];
    uint32_t sbase = smem_to_u32(smem);
    __shared__ int s_vid[128];
    const int tid = threadIdx.x, wid = tid >> 5, lane = tid & 31;
    const int warp_m = wid & 3, warp_n = wid >> 2;
    const int arow0 = blockIdx.y * 128, bcol0 = blockIdx.x * 128;

    float acc[2][8][4] = {};
    mma_mainloop(g_B1, arow0, bcol0, sbase, acc, tid, lane, warp_m, warp_n);

    // dump fragments to smem [128 rows][stride 132]
    float* s_acc = reinterpret_cast<float*>(smem);
    const int lr4 = lane >> 2, lc2 = (lane & 3) * 2;
#pragma unroll
    for (int mi = 0; mi < 2; mi++) {
        int r0 = warp_m * 32 + mi * 16 + lr4;
#pragma unroll
        for (int nj = 0; nj < 8; nj++) {
            int col = warp_n * 64 + nj * 8 + lc2;
            s_acc[r0 * 132 + col]           = acc[mi][nj][0];
            s_acc[r0 * 132 + col + 1]       = acc[mi][nj][1];
            s_acc[(r0 + 8) * 132 + col]     = acc[mi][nj][2];
            s_acc[(r0 + 8) * 132 + col + 1] = acc[mi][nj][3];
        }
    }
    if (tid < 128) s_vid[tid] = __ldg(&g_svid[arow0 + tid]);
    __syncthreads();

    // per-column run-max over sorted rows: ~1 atomic per (vertex run, col)
    const int col = tid & 127;
    const int rbeg = (tid >> 7) * 64;
    int vcur = s_vid[rbeg];
    float cur = s_acc[rbeg * 132 + col];
    for (int r = rbeg + 1; r < rbeg + 64; r++) {
        int v = s_vid[r];
        float val = s_acc[r * 132 + col];
        if (v != vcur) {
            atomicMaxFloat(&g_zvmax[(size_t)vcur * C_MID + bcol0 + col], cur);
            vcur = v;
            cur = val;
        } else {
            cur = fmaxf(cur, val);
        }
    }
    atomicMaxFloat(&g_zvmax[(size_t)vcur * C_MID + bcol0 + col], cur);
}

// ---------------- GEMM3: out[order[p]] = xs@W2e^T + z_vertex[svid[p]] ----------------
__global__ void __launch_bounds__(256, 2)
k_mma3(float* __restrict__ out) {
    extern __shared__ char smem[];
    uint32_t sbase = smem_to_u32(smem);
    const int tid = threadIdx.x, wid = tid >> 5, lane = tid & 31;
    const int warp_m = wid & 3, warp_n = wid >> 2;
    const int arow0 = blockIdx.y * 128;

    float acc[2][8][4] = {};
    mma_mainloop(g_B3, arow0, 0, sbase, acc, tid, lane, warp_m, warp_n);

    const int lr4 = lane >> 2, lc2 = (lane & 3) * 2;
#pragma unroll
    for (int mi = 0; mi < 2; mi++) {
        int r0 = arow0 + warp_m * 32 + mi * 16 + lr4;
        int r1 = r0 + 8;
        int v0 = __ldg(&g_svid[r0]);
        int v1 = __ldg(&g_svid[r1]);
        int e0 = __ldg(&g_order[r0]);
        int e1 = __ldg(&g_order[r1]);
        const float* z0 = g_zvertex + (size_t)v0 * C_OUT + warp_n * 64 + lc2;
        const float* z1 = g_zvertex + (size_t)v1 * C_OUT + warp_n * 64 + lc2;
        float* o0 = out + (size_t)e0 * C_OUT + warp_n * 64 + lc2;
        float* o1 = out + (size_t)e1 * C_OUT + warp_n * 64 + lc2;
#pragma unroll
        for (int nj = 0; nj < 8; nj++) {
            float2 za = __ldg(reinterpret_cast<const float2*>(z0 + nj * 8));
            float2 zb = __ldg(reinterpret_cast<const float2*>(z1 + nj * 8));
            *reinterpret_cast<float2*>(o0 + nj * 8) =
                make_float2(acc[mi][nj][0] + za.x, acc[mi][nj][1] + za.y);
            *reinterpret_cast<float2*>(o1 + nj * 8) =
                make_float2(acc[mi][nj][2] + zb.x, acc[mi][nj][3] + zb.y);
        }
    }
}

// ---------------- GEMM2 (FFMA, small): z_vertex = fix(z_vmax + b1) @ W2v^T ----------------
#define FMA_F32X2(d, a, b) asm("fma.rn.f32x2 %0, %1, %2, %0;" : "+l"(d) : "l"(a), "l"(b))
#define DUP_F32X2(d, s)    asm("mov.b64 %0, {%1, %1};" : "=l"(d) : "f"(s))
__device__ __forceinline__ float lo32(unsigned long long v) {
    return __uint_as_float((unsigned)(v & 0xffffffffull));
}
__device__ __forceinline__ float hi32(unsigned long long v) {
    return __uint_as_float((unsigned)(v >> 32));
}

__global__ void __launch_bounds__(256, 2)
k_gemm2(const float* __restrict__ b1) {
    __shared__ float As[16][132];
    __shared__ float Bs[16][128];
    unsigned long long acc[8][4] = {};
    const int arow0 = blockIdx.x * 128;
    const int tid = threadIdx.x;
    const int tr = (tid >> 4) << 3, tc = (tid & 15) << 3;
    const int lrow = tid >> 1, lf4 = (tid & 1) << 1;
    const int brow = tid >> 4, bc4 = tid & 15;

    for (int k0 = 0; k0 < C_MID; k0 += 16) {
        const float4* asrc = reinterpret_cast<const float4*>(
            g_zvmax + (size_t)(arow0 + lrow) * C_MID + k0);
        float4 v0 = __ldg(asrc + lf4);
        float4 v1 = __ldg(asrc + lf4 + 1);
        float4 bb0 = *reinterpret_cast<const float4*>(&b1[k0 + lf4 * 4]);
        float4 bb1 = *reinterpret_cast<const float4*>(&b1[k0 + lf4 * 4 + 4]);
        v0.x = (v0.x < -1e38f) ? 0.0f : v0.x + bb0.x;
        v0.y = (v0.y < -1e38f) ? 0.0f : v0.y + bb0.y;
        v0.z = (v0.z < -1e38f) ? 0.0f : v0.z + bb0.z;
        v0.w = (v0.w < -1e38f) ? 0.0f : v0.w + bb0.w;
        v1.x = (v1.x < -1e38f) ? 0.0f : v1.x + bb1.x;
        v1.y = (v1.y < -1e38f) ? 0.0f : v1.y + bb1.y;
        v1.z = (v1.z < -1e38f) ? 0.0f : v1.z + bb1.z;
        v1.w = (v1.w < -1e38f) ? 0.0f : v1.w + bb1.w;
        {
            int kk = lf4 << 2;
            As[kk + 0][lrow] = v0.x;  As[kk + 1][lrow] = v0.y;
            As[kk + 2][lrow] = v0.z;  As[kk + 3][lrow] = v0.w;
            As[kk + 4][lrow] = v1.x;  As[kk + 5][lrow] = v1.y;
            As[kk + 6][lrow] = v1.z;  As[kk + 7][lrow] = v1.w;
        }
        const float4* bsrc = reinterpret_cast<const float4*>(
            g_Wt2v + (size_t)(k0 + brow) * C_OUT);
        float4 w0 = __ldg(bsrc + bc4);
        float4 w1 = __ldg(bsrc + bc4 + 16);
        *reinterpret_cast<float4*>(&Bs[brow][(bc4 << 2)])      = w0;
        *reinterpret_cast<float4*>(&Bs[brow][(bc4 << 2) + 64]) = w1;
        __syncthreads();
#pragma unroll
        for (int k = 0; k < 16; k++) {
            float4 aq0 = *reinterpret_cast<const float4*>(&As[k][tr]);
            float4 aq1 = *reinterpret_cast<const float4*>(&As[k][tr + 4]);
            ulonglong2 b0 = *reinterpret_cast<const ulonglong2*>(&Bs[k][tc]);
            ulonglong2 b1v = *reinterpret_cast<const ulonglong2*>(&Bs[k][tc + 4]);
            unsigned long long b2[4] = {b0.x, b0.y, b1v.x, b1v.y};
            float af[8] = {aq0.x, aq0.y, aq0.z, aq0.w, aq1.x, aq1.y, aq1.z, aq1.w};
            unsigned long long a2[8];
#pragma unroll
            for (int i = 0; i < 8; i++) DUP_F32X2(a2[i], af[i]);
#pragma unroll
            for (int i = 0; i < 8; i++)
#pragma unroll
                for (int j = 0; j < 4; j++) FMA_F32X2(acc[i][j], a2[i], b2[j]);
        }
        __syncthreads();
    }
#pragma unroll
    for (int i = 0; i < 8; i++) {
        int vrow = arow0 + tr + i;
        if (vrow < V_SEG) {
            float4 o0 = make_float4(lo32(acc[i][0]), hi32(acc[i][0]),
                                    lo32(acc[i][1]), hi32(acc[i][1]));
            float4 o1 = make_float4(lo32(acc[i][2]), hi32(acc[i][2]),
                                    lo32(acc[i][3]), hi32(acc[i][3]));
            *reinterpret_cast<float4*>(&g_zvertex[(size_t)vrow * C_OUT + tc])     = o0;
            *reinterpret_cast<float4*>(&g_zvertex[(size_t)vrow * C_OUT + tc + 4]) = o1;
        }
    }
}

// ---------------- launch ----------------
static constexpr int SMEM1 = 128 * 132 * 4;   // 67584 (mainloop 64KB + padded epilogue)
static constexpr int SMEM3 = 65536;

extern "C" void kernel_launch(void* const* d_in, const int* in_sizes, int n_in,
                              void* d_out, int out_size) {
    const float* x   = (const float*)d_in[0];
    const int*   vid = (const int*)d_in[1];
    const float* W1  = (const float*)d_in[2];
    const float* b1  = (const float*)d_in[3];
    const float* W2e = (const float*)d_in[4];
    const float* W2v = (const float*)d_in[5];
    float* out = (float*)d_out;

    cudaFuncSetAttribute(k_mma1, cudaFuncAttributeMaxDynamicSharedMemorySize, SMEM1);
    cudaFuncSetAttribute(k_mma3, cudaFuncAttributeMaxDynamicSharedMemorySize, SMEM3);

    k_prep_w<<<128, 256>>>(W1, W2e, W2v);
    k_zero_count<<<(V_PAD + 255) / 256, 256>>>();
    k_hist<<<E_EDGES / 256, 256>>>(vid);
    k_scan<<<1, 1024>>>();
    k_scatter<<<E_EDGES / 256, 256>>>(vid);
    k_split_x<<<(E_EDGES * C_IN / 4) / 256, 256>>>(x);
    k_init_zvmax<<<(V_PAD * C_MID / 4 + 255) / 256, 256>>>();
    k_mma1<<<dim3(2, E_EDGES / 128), 256, SMEM1>>>();
    k_gemm2<<<V_PAD / 128, 256>>>(b1);
    k_mma3<<<dim3(1, E_EDGES / 128), 256, SMEM3>>>(out);
}